// round 8
// baseline (speedup 1.0000x reference)
#include <cuda_runtime.h>
#include <cuda_bf16.h>
#include <math.h>
#include <stdint.h>

// Problem constants
#define B_ 512
#define T_ 256
#define H_ 512
#define E_ 10
#define V_ 10000
#define C_ 10
#define NGATE 4
#define N_TOT (NGATE * H_)   // 2048; layout n = 4*j + gate (gates interleaved)

// ---------------------------------------------------------------------------
// Device-global state & scratch (no allocations allowed)
// ---------------------------------------------------------------------------
__device__ float g_c[B_ * H_];
__device__ __nv_bfloat16 g_hhi[2][B_ * H_];   // ping-pong (cross-block hazard)
__device__ __nv_bfloat16 g_hlo[2][B_ * H_];
__device__ __nv_bfloat16 g_Wthi[N_TOT * H_];  // W^T split-hi: [n=4j+g][k]
__device__ __nv_bfloat16 g_Wtlo[N_TOT * H_];  // W^T split-lo

// ---------------------------------------------------------------------------
// One-time weight transpose + bf16 hi/lo split: g_Wt[(4j+g)][k] = Wh_g[k][j]
// ---------------------------------------------------------------------------
__global__ void prep_weights_kernel(
    const float* __restrict__ Wgh, const float* __restrict__ Wih,
    const float* __restrict__ Wfh, const float* __restrict__ Woh)
{
    __shared__ float tile[32][33];
    const float* const W[4] = {Wgh, Wih, Wfh, Woh};
    const int g = blockIdx.z;
    const int j0 = blockIdx.x * 32;
    const int k0 = blockIdx.y * 32;
    const int tx = threadIdx.x, ty = threadIdx.y;

    tile[ty][tx] = W[g][(k0 + ty) * H_ + j0 + tx];
    __syncthreads();

    float w = tile[tx][ty];                       // = W[k0+tx][j0+ty]
    __nv_bfloat16 hi = __float2bfloat16(w);
    __nv_bfloat16 lo = __float2bfloat16(w - __bfloat162float(hi));
    int n = 4 * (j0 + ty) + g;
    g_Wthi[n * H_ + k0 + tx] = hi;
    g_Wtlo[n * H_ + k0 + tx] = lo;
}

__global__ void init_state_kernel() {
    int i = blockIdx.x * blockDim.x + threadIdx.x;
    if (i < B_ * H_) {
        g_c[i] = 0.0f;
        g_hhi[0][i] = __float2bfloat16(0.0f);
        g_hlo[0][i] = __float2bfloat16(0.0f);
    }
}

__device__ __forceinline__ void cp16(void* smem_dst, const void* gmem_src) {
    uint32_t s = (uint32_t)__cvta_generic_to_shared(smem_dst);
    asm volatile("cp.async.cg.shared.global [%0], [%1], 16;" :: "r"(s), "l"(gmem_src));
}

__device__ __forceinline__ void ldm_x4(uint32_t r[4], uint32_t addr) {
    asm volatile("ldmatrix.sync.aligned.m8n8.x4.shared.b16 {%0,%1,%2,%3}, [%4];"
                 : "=r"(r[0]), "=r"(r[1]), "=r"(r[2]), "=r"(r[3]) : "r"(addr));
}

__device__ __forceinline__ void mma_bf16(
    float c[4], const uint32_t a[4], uint32_t b0, uint32_t b1)
{
    asm volatile(
        "mma.sync.aligned.m16n8k16.row.col.f32.bf16.bf16.f32 "
        "{%0,%1,%2,%3}, {%4,%5,%6,%7}, {%8,%9}, {%0,%1,%2,%3};"
        : "+f"(c[0]), "+f"(c[1]), "+f"(c[2]), "+f"(c[3])
        : "r"(a[0]), "r"(a[1]), "r"(a[2]), "r"(a[3]), "r"(b0), "r"(b1));
}

// ---------------------------------------------------------------------------
// Fully fused LSTM step. Block tile 64(M) x 128(N = 32 j x 4 gates),
// 16 warps (warp tile 16x32), k-chunks of 32, 3-stage cp.async pipeline
// (wait_group 1, ONE barrier per chunk), hoisted ldmatrix, split-bf16 3-term.
// Grid (16, 8) = 128 blocks, single wave, 4 warps/SMSP.
// ---------------------------------------------------------------------------
#define GBM 64
#define GBN 128
#define GKC 32
#define APAD 40
#define NT 512
#define STAGES 3
#define A_STAGE_BYTES (2 * GBM * APAD * 2)      // hi+lo: 10240 B
#define B_STAGE_BYTES (2 * GBN * APAD * 2)      // hi+lo: 20480 B
#define STAGE_BYTES (A_STAGE_BYTES + B_STAGE_BYTES)   // 30720 B
#define A_OFF 0
#define B_OFF A_STAGE_BYTES
#define A_HL (GBM * APAD * 2)                   // 5120 B
#define B_HL (GBN * APAD * 2)                   // 10240 B
#define MAIN_SMEM_BYTES (STAGES * STAGE_BYTES)  // 92160 B
#define ZPAD 132
#define EXTRA_FLOATS (GBM * E_ + NGATE * E_ * 32 + NGATE * 32)  // 2048
#define FUSED_SMEM_BYTES (MAIN_SMEM_BYTES + EXTRA_FLOATS * 4)   // 100352 B

__global__ void __launch_bounds__(NT) lstm_fused_step(
    int t, int src,
    const int* __restrict__ x, const float* __restrict__ emb,
    const float* __restrict__ Wgx, const float* __restrict__ Wix,
    const float* __restrict__ Wfx, const float* __restrict__ Wox,
    const float* __restrict__ bg, const float* __restrict__ bi,
    const float* __restrict__ bf_, const float* __restrict__ bo)
{
    extern __shared__ char smem_raw[];
    float* const z_s    = (float*)smem_raw;                     // epilogue alias
    float* const xe_s   = (float*)(smem_raw + MAIN_SMEM_BYTES); // [64][E_]
    float* const xw_s   = xe_s + GBM * E_;                      // [4][E_][32]
    float* const bias_s = xw_s + NGATE * E_ * 32;               // [4][32]

    const int tid = threadIdx.x;
    const int bn = blockIdx.x * GBN;    // col base (n = 4j+g)
    const int bj = blockIdx.x * 32;     // j base
    const int bb = blockIdx.y * GBM;    // batch base
    const int w = tid >> 5;
    const int lane = tid & 31;
    const int gid = lane >> 2;
    const int tig = lane & 3;
    const int wm = (w >> 2) * 16;       // 4 m-groups
    const int wn = (w & 3) * 32;        // 4 n-groups

    const __nv_bfloat16* __restrict__ hhi = g_hhi[src];
    const __nv_bfloat16* __restrict__ hlo = g_hlo[src];
    __nv_bfloat16* __restrict__ hhi_out = g_hhi[src ^ 1];
    __nv_bfloat16* __restrict__ hlo_out = g_hlo[src ^ 1];

    const uint32_t SBase = (uint32_t)__cvta_generic_to_shared(smem_raw);

    // per-lane ldmatrix fragment offsets (bytes, relative to stage base)
    const uint32_t a_frag = A_OFF +
        ((wm + ((lane >> 3) & 1) * 8 + (lane & 7)) * APAD + ((lane >> 4) & 1) * 8) * 2;
    const uint32_t b_frag0 = B_OFF +
        ((wn + ((lane >> 4) & 1) * 8 + (lane & 7)) * APAD + ((lane >> 3) & 1) * 8) * 2;
    const uint32_t b_frag1 = b_frag0 + 16 * APAD * 2;   // +16 n rows

    // per-thread cp.async slots
    const int a_hl = tid >> 8, a_r = (tid >> 2) & 63, a_s = (tid & 3) * 8;
    char* const smem_c = smem_raw;

    auto load_chunk = [&](int stage, int k0) {
        char* sb = smem_c + stage * STAGE_BYTES;
        {
            const __nv_bfloat16* srcp = a_hl ? hlo : hhi;
            cp16(sb + A_OFF + a_hl * A_HL + (a_r * APAD + a_s) * 2,
                 &srcp[(bb + a_r) * H_ + k0 + a_s]);
        }
        #pragma unroll
        for (int half = 0; half < 2; half++) {
            int idx = tid + half * NT;
            int hl = idx >> 9, br = (idx >> 2) & 127, bs = (idx & 3) * 8;
            const __nv_bfloat16* srcp = hl ? g_Wtlo : g_Wthi;
            cp16(sb + B_OFF + hl * B_HL + (br * APAD + bs) * 2,
                 &srcp[(bn + br) * H_ + k0 + bs]);
        }
        asm volatile("cp.async.commit_group;");
    };

    // prologue: 2 chunks in flight
    load_chunk(0, 0);
    load_chunk(1, GKC);

    // ---- stage epilogue operands (disjoint smem; overlaps pipeline) ----
    for (int i = tid; i < GBM * E_; i += NT) {
        int r = i / E_, e = i % E_;
        int idx = x[(bb + r) * T_ + t];
        idx = min(max(idx, 0), V_ - 1);
        xe_s[r * E_ + e] = emb[idx * E_ + e];
    }
    {
        const float* const Wx[4] = {Wgx, Wix, Wfx, Wox};
        for (int i = tid; i < NGATE * E_ * 32; i += NT) {
            int g = i / (E_ * 32), rem = i % (E_ * 32);
            int e = rem / 32, jl = rem % 32;
            xw_s[i] = Wx[g][e * H_ + bj + jl];
        }
        const float* const bptr[4] = {bg, bi, bf_, bo};
        if (tid < NGATE * 32) {
            int g = tid / 32, jl = tid % 32;
            bias_s[tid] = bptr[g][bj + jl];
        }
    }

    float acc[4][4];
    #pragma unroll
    for (int nf = 0; nf < 4; nf++)
        #pragma unroll
        for (int v = 0; v < 4; v++) acc[nf][v] = 0.0f;

    // ---- recurrent GEMM mainloop: 16 chunks, 3-stage pipeline ----
    const int NCH = H_ / GKC;   // 16
    #pragma unroll 1
    for (int kt = 0; kt < NCH; kt++) {
        if (kt < NCH - 2) {
            asm volatile("cp.async.wait_group 1;" ::: "memory");
        } else {
            asm volatile("cp.async.wait_group 0;" ::: "memory");
        }
        __syncthreads();                       // chunk kt visible to all warps
        if (kt + 2 < NCH) load_chunk((kt + 2) % STAGES, (kt + 2) * GKC);

        const uint32_t sb = SBase + (kt % STAGES) * STAGE_BYTES;

        // hoisted fragment loads: 12 ldmatrix for the whole chunk
        uint32_t AH[2][4], AL[2][4], BH[2][2][4], BL[2][2][4];
        #pragma unroll
        for (int kk2 = 0; kk2 < 2; kk2++) {
            const uint32_t ko = kk2 * 32;      // 16 bf16 = 32 bytes
            ldm_x4(AH[kk2], sb + a_frag + ko);
            ldm_x4(AL[kk2], sb + a_frag + ko + A_HL);
            ldm_x4(BH[kk2][0], sb + b_frag0 + ko);
            ldm_x4(BL[kk2][0], sb + b_frag0 + ko + B_HL);
            ldm_x4(BH[kk2][1], sb + b_frag1 + ko);
            ldm_x4(BL[kk2][1], sb + b_frag1 + ko + B_HL);
        }

        // 24-MMA burst; rounds cycle the 4 accumulator chains for ILP
        #pragma unroll
        for (int kk2 = 0; kk2 < 2; kk2++) {
            #pragma unroll
            for (int t3 = 0; t3 < 3; t3++) {
                const uint32_t* a = (t3 == 2) ? AL[kk2] : AH[kk2];
                #pragma unroll
                for (int p = 0; p < 2; p++) {
                    const uint32_t* b = (t3 == 1) ? BL[kk2][p] : BH[kk2][p];
                    mma_bf16(acc[2 * p],     a, b[0], b[1]);
                    mma_bf16(acc[2 * p + 1], a, b[2], b[3]);
                }
            }
        }
    }
    __syncthreads();   // all MMAs done before z_s aliases stage memory

    // ---- spill accs to smem (aliased over dead pipeline stages) ----
    {
        const int row_l = wm + gid;
        #pragma unroll
        for (int nf = 0; nf < 4; nf++) {
            const int col = wn + nf * 8 + 2 * tig;
            *(float2*)&z_s[row_l * ZPAD + col] =
                make_float2(acc[nf][0], acc[nf][1]);
            *(float2*)&z_s[(row_l + 8) * ZPAD + col] =
                make_float2(acc[nf][2], acc[nf][3]);
        }
    }
    __syncthreads();

    // ---- fused pointwise: x-proj + bias + activations + c/h update ----
    #pragma unroll
    for (int rep = 0; rep < (GBM * 32) / NT; rep++) {   // 4 reps
        const int elem = tid + rep * NT;
        const int r = elem >> 5, jl = elem & 31;
        const int gr = bb + r, gj = bj + jl;

        float zg = z_s[r * ZPAD + 4 * jl + 0] + bias_s[0 * 32 + jl];
        float zi = z_s[r * ZPAD + 4 * jl + 1] + bias_s[1 * 32 + jl];
        float zf = z_s[r * ZPAD + 4 * jl + 2] + bias_s[2 * 32 + jl];
        float zo = z_s[r * ZPAD + 4 * jl + 3] + bias_s[3 * 32 + jl];

        #pragma unroll
        for (int e = 0; e < E_; e++) {
            float xv = xe_s[r * E_ + e];
            zg += xv * xw_s[0 * E_ * 32 + e * 32 + jl];
            zi += xv * xw_s[1 * E_ * 32 + e * 32 + jl];
            zf += xv * xw_s[2 * E_ * 32 + e * 32 + jl];
            zo += xv * xw_s[3 * E_ * 32 + e * 32 + jl];
        }

        float gg = tanhf(zg);
        float ii = 1.0f / (1.0f + __expf(-zi));
        float ff = 1.0f / (1.0f + __expf(-zf));
        float oo = 1.0f / (1.0f + __expf(-zo));

        float cn = gg * ii + g_c[gr * H_ + gj] * ff;
        float hn = tanhf(cn) * oo;

        g_c[gr * H_ + gj] = cn;
        __nv_bfloat16 hi = __float2bfloat16(hn);
        hhi_out[gr * H_ + gj] = hi;
        hlo_out[gr * H_ + gj] = __float2bfloat16(hn - __bfloat162float(hi));
    }
}

// ---------------------------------------------------------------------------
// Final projection: h reconstructed as hi+lo from buffer 0 (after t=255).
// ---------------------------------------------------------------------------
__global__ void proj_kernel(const float* __restrict__ Wph,
                            const float* __restrict__ bp, float* __restrict__ out) {
    int i = blockIdx.x * blockDim.x + threadIdx.x;
    if (i >= B_ * C_) return;
    int b = i / C_;
    int c = i % C_;
    float acc = bp[c];
    #pragma unroll 8
    for (int k = 0; k < H_; k++) {
        float h = __bfloat162float(g_hhi[0][b * H_ + k]) +
                  __bfloat162float(g_hlo[0][b * H_ + k]);
        acc += h * Wph[k * C_ + c];
    }
    out[i] = acc;
}

// ---------------------------------------------------------------------------
// Launch sequence (graph-capturable, single stream)
// ---------------------------------------------------------------------------
extern "C" void kernel_launch(void* const* d_in, const int* in_sizes, int n_in,
                              void* d_out, int out_size) {
    const int* x        = (const int*)d_in[0];       // int32 (JAX downcasts int64)
    const float* emb    = (const float*)d_in[1];
    const float* Wgx    = (const float*)d_in[2];
    const float* Wgh    = (const float*)d_in[3];
    const float* bg     = (const float*)d_in[4];
    const float* Wix    = (const float*)d_in[5];
    const float* Wih    = (const float*)d_in[6];
    const float* bi     = (const float*)d_in[7];
    const float* Wfx    = (const float*)d_in[8];
    const float* Wfh    = (const float*)d_in[9];
    const float* bf_    = (const float*)d_in[10];
    const float* Wox    = (const float*)d_in[11];
    const float* Woh    = (const float*)d_in[12];
    const float* bo     = (const float*)d_in[13];
    const float* Wph    = (const float*)d_in[14];
    const float* bp     = (const float*)d_in[15];
    float* out          = (float*)d_out;

    static bool attr_set = false;
    if (!attr_set) {
        cudaFuncSetAttribute(lstm_fused_step,
                             cudaFuncAttributeMaxDynamicSharedMemorySize,
                             FUSED_SMEM_BYTES);
        attr_set = true;
    }

    {
        dim3 tgrid(H_ / 32, H_ / 32, NGATE);
        dim3 tblk(32, 32);
        prep_weights_kernel<<<tgrid, tblk>>>(Wgh, Wih, Wfh, Woh);
    }
    init_state_kernel<<<(B_ * H_ + 255) / 256, 256>>>();

    dim3 ggrid(N_TOT / GBN, B_ / GBM);   // (16, 8) = 128 blocks
    for (int t = 0; t < T_; t++) {
        lstm_fused_step<<<ggrid, NT, FUSED_SMEM_BYTES>>>(
            t, t & 1, x, emb, Wgx, Wix, Wfx, Wox, bg, bi, bf_, bo);
    }

    proj_kernel<<<(B_ * C_ + 255) / 256, 256>>>(Wph, bp, out);
}

// round 9
// speedup vs baseline: 1.0337x; 1.0337x over previous
#include <cuda_runtime.h>
#include <cuda_bf16.h>
#include <math.h>
#include <stdint.h>

// Problem constants
#define B_ 512
#define T_ 256
#define H_ 512
#define E_ 10
#define V_ 10000
#define C_ 10
#define NGATE 4
#define N_TOT (NGATE * H_)   // 2048; layout n = 4*j + gate (gates interleaved)

// ---------------------------------------------------------------------------
// Device-global state & scratch (no allocations allowed)
// ---------------------------------------------------------------------------
__device__ float g_c[B_ * H_];
__device__ __nv_bfloat16 g_hhi[2][B_ * H_];   // ping-pong (cross-block hazard)
__device__ __nv_bfloat16 g_hlo[2][B_ * H_];
__device__ __nv_bfloat16 g_Wthi[N_TOT * H_];  // W^T split-hi: [n=4j+g][k]
__device__ __nv_bfloat16 g_Wtlo[N_TOT * H_];  // W^T split-lo

// ---------------------------------------------------------------------------
// One-time weight transpose + bf16 hi/lo split: g_Wt[(4j+g)][k] = Wh_g[k][j]
// ---------------------------------------------------------------------------
__global__ void prep_weights_kernel(
    const float* __restrict__ Wgh, const float* __restrict__ Wih,
    const float* __restrict__ Wfh, const float* __restrict__ Woh)
{
    __shared__ float tile[32][33];
    const float* const W[4] = {Wgh, Wih, Wfh, Woh};
    const int g = blockIdx.z;
    const int j0 = blockIdx.x * 32;
    const int k0 = blockIdx.y * 32;
    const int tx = threadIdx.x, ty = threadIdx.y;

    tile[ty][tx] = W[g][(k0 + ty) * H_ + j0 + tx];
    __syncthreads();

    float w = tile[tx][ty];                       // = W[k0+tx][j0+ty]
    __nv_bfloat16 hi = __float2bfloat16(w);
    __nv_bfloat16 lo = __float2bfloat16(w - __bfloat162float(hi));
    int n = 4 * (j0 + ty) + g;
    g_Wthi[n * H_ + k0 + tx] = hi;
    g_Wtlo[n * H_ + k0 + tx] = lo;
}

__global__ void init_state_kernel() {
    int i = blockIdx.x * blockDim.x + threadIdx.x;
    if (i < B_ * H_) {
        g_c[i] = 0.0f;
        g_hhi[0][i] = __float2bfloat16(0.0f);
        g_hlo[0][i] = __float2bfloat16(0.0f);
    }
}

__device__ __forceinline__ void cp16(void* smem_dst, const void* gmem_src) {
    uint32_t s = (uint32_t)__cvta_generic_to_shared(smem_dst);
    asm volatile("cp.async.cg.shared.global [%0], [%1], 16;" :: "r"(s), "l"(gmem_src));
}

__device__ __forceinline__ void ldm_x4(uint32_t r[4], uint32_t addr) {
    asm volatile("ldmatrix.sync.aligned.m8n8.x4.shared.b16 {%0,%1,%2,%3}, [%4];"
                 : "=r"(r[0]), "=r"(r[1]), "=r"(r[2]), "=r"(r[3]) : "r"(addr));
}

__device__ __forceinline__ void mma_bf16(
    float c[4], const uint32_t a[4], uint32_t b0, uint32_t b1)
{
    asm volatile(
        "mma.sync.aligned.m16n8k16.row.col.f32.bf16.bf16.f32 "
        "{%0,%1,%2,%3}, {%4,%5,%6,%7}, {%8,%9}, {%0,%1,%2,%3};"
        : "+f"(c[0]), "+f"(c[1]), "+f"(c[2]), "+f"(c[3])
        : "r"(a[0]), "r"(a[1]), "r"(a[2]), "r"(a[3]), "r"(b0), "r"(b1));
}

// ---------------------------------------------------------------------------
// Fully fused LSTM step. Block tile 64(M) x 64(N = 16 j x 4 gates),
// 8 warps (warp tile 16x32), k-chunks of 32, 3-stage cp.async pipeline,
// hoisted ldmatrix, split-bf16 3-term MMA.
// Grid (2048/64, 512/64) = (32, 8) = 256 blocks -> ~2 blocks/SM,
// 8 warps/SMSP on loaded SMs (2x latency hiding vs previous round).
// ---------------------------------------------------------------------------
#define GBM 64
#define GBN 64
#define GKC 32
#define APAD 40
#define NT 256
#define STAGES 3
#define A_STAGE_BYTES (2 * GBM * APAD * 2)      // hi+lo: 10240 B
#define B_STAGE_BYTES (2 * GBN * APAD * 2)      // hi+lo: 10240 B
#define STAGE_BYTES (A_STAGE_BYTES + B_STAGE_BYTES)   // 20480 B
#define A_OFF 0
#define B_OFF A_STAGE_BYTES
#define A_HL (GBM * APAD * 2)                   // 5120 B
#define B_HL (GBN * APAD * 2)                   // 5120 B
#define MAIN_SMEM_BYTES (STAGES * STAGE_BYTES)  // 61440 B
#define JB (GBN / NGATE)                        // 16 j per block
#define ZPAD 68
#define EXTRA_FLOATS (GBM * E_ + NGATE * E_ * JB + NGATE * JB)  // 640+640+64
#define FUSED_SMEM_BYTES (MAIN_SMEM_BYTES + EXTRA_FLOATS * 4)   // 66816 B

__global__ void __launch_bounds__(NT, 2) lstm_fused_step(
    int t, int src,
    const int* __restrict__ x, const float* __restrict__ emb,
    const float* __restrict__ Wgx, const float* __restrict__ Wix,
    const float* __restrict__ Wfx, const float* __restrict__ Wox,
    const float* __restrict__ bg, const float* __restrict__ bi,
    const float* __restrict__ bf_, const float* __restrict__ bo)
{
    extern __shared__ char smem_raw[];
    float* const z_s    = (float*)smem_raw;                     // epilogue alias
    float* const xe_s   = (float*)(smem_raw + MAIN_SMEM_BYTES); // [64][E_]
    float* const xw_s   = xe_s + GBM * E_;                      // [4][E_][JB]
    float* const bias_s = xw_s + NGATE * E_ * JB;               // [4][JB]

    const int tid = threadIdx.x;
    const int bn = blockIdx.x * GBN;    // col base (n = 4j+g)
    const int bj = blockIdx.x * JB;     // j base
    const int bb = blockIdx.y * GBM;    // batch base
    const int w = tid >> 5;
    const int lane = tid & 31;
    const int gid = lane >> 2;
    const int tig = lane & 3;
    const int wm = (w >> 1) * 16;       // 4 m-groups
    const int wn = (w & 1) * 32;        // 2 n-groups

    const __nv_bfloat16* __restrict__ hhi = g_hhi[src];
    const __nv_bfloat16* __restrict__ hlo = g_hlo[src];
    __nv_bfloat16* __restrict__ hhi_out = g_hhi[src ^ 1];
    __nv_bfloat16* __restrict__ hlo_out = g_hlo[src ^ 1];

    const uint32_t SBase = (uint32_t)__cvta_generic_to_shared(smem_raw);

    // per-lane ldmatrix fragment offsets (bytes, relative to stage base)
    const uint32_t a_frag = A_OFF +
        ((wm + ((lane >> 3) & 1) * 8 + (lane & 7)) * APAD + ((lane >> 4) & 1) * 8) * 2;
    const uint32_t b_frag0 = B_OFF +
        ((wn + ((lane >> 4) & 1) * 8 + (lane & 7)) * APAD + ((lane >> 3) & 1) * 8) * 2;
    const uint32_t b_frag1 = b_frag0 + 16 * APAD * 2;   // +16 n rows

    char* const smem_c = smem_raw;

    auto load_chunk = [&](int stage, int k0) {
        char* sb = smem_c + stage * STAGE_BYTES;
        // A: 2hl * 64r * 32k bf16 = 512 x 16B segs -> 2 per thread
        #pragma unroll
        for (int half = 0; half < 2; half++) {
            int idx = tid + half * NT;
            int hl = idx >> 8, r = (idx >> 2) & 63, s = (idx & 3) * 8;
            const __nv_bfloat16* srcp = hl ? hlo : hhi;
            cp16(sb + A_OFF + hl * A_HL + (r * APAD + s) * 2,
                 &srcp[(bb + r) * H_ + k0 + s]);
        }
        // B: 2hl * 64r * 32k = 512 segs -> 2 per thread
        #pragma unroll
        for (int half = 0; half < 2; half++) {
            int idx = tid + half * NT;
            int hl = idx >> 8, br = (idx >> 2) & 63, bs = (idx & 3) * 8;
            const __nv_bfloat16* srcp = hl ? g_Wtlo : g_Wthi;
            cp16(sb + B_OFF + hl * B_HL + (br * APAD + bs) * 2,
                 &srcp[(bn + br) * H_ + k0 + bs]);
        }
        asm volatile("cp.async.commit_group;");
    };

    // prologue: 2 chunks in flight
    load_chunk(0, 0);
    load_chunk(1, GKC);

    // ---- stage epilogue operands (disjoint smem; overlaps pipeline) ----
    for (int i = tid; i < GBM * E_; i += NT) {
        int r = i / E_, e = i % E_;
        int idx = x[(bb + r) * T_ + t];
        idx = min(max(idx, 0), V_ - 1);
        xe_s[r * E_ + e] = emb[idx * E_ + e];
    }
    {
        const float* const Wx[4] = {Wgx, Wix, Wfx, Wox};
        for (int i = tid; i < NGATE * E_ * JB; i += NT) {
            int g = i / (E_ * JB), rem = i % (E_ * JB);
            int e = rem / JB, jl = rem % JB;
            xw_s[i] = Wx[g][e * H_ + bj + jl];
        }
        const float* const bptr[4] = {bg, bi, bf_, bo};
        if (tid < NGATE * JB) {
            int g = tid / JB, jl = tid % JB;
            bias_s[tid] = bptr[g][bj + jl];
        }
    }

    float acc[4][4];
    #pragma unroll
    for (int nf = 0; nf < 4; nf++)
        #pragma unroll
        for (int v = 0; v < 4; v++) acc[nf][v] = 0.0f;

    // ---- recurrent GEMM mainloop: 16 chunks, 3-stage pipeline ----
    const int NCH = H_ / GKC;   // 16
    #pragma unroll 1
    for (int kt = 0; kt < NCH; kt++) {
        if (kt < NCH - 2) {
            asm volatile("cp.async.wait_group 1;" ::: "memory");
        } else {
            asm volatile("cp.async.wait_group 0;" ::: "memory");
        }
        __syncthreads();                       // chunk kt visible to all warps
        if (kt + 2 < NCH) load_chunk((kt + 2) % STAGES, (kt + 2) * GKC);

        const uint32_t sb = SBase + (kt % STAGES) * STAGE_BYTES;

        // hoisted fragment loads: 12 ldmatrix for the whole chunk
        uint32_t AH[2][4], AL[2][4], BH[2][2][4], BL[2][2][4];
        #pragma unroll
        for (int kk2 = 0; kk2 < 2; kk2++) {
            const uint32_t ko = kk2 * 32;      // 16 bf16 = 32 bytes
            ldm_x4(AH[kk2], sb + a_frag + ko);
            ldm_x4(AL[kk2], sb + a_frag + ko + A_HL);
            ldm_x4(BH[kk2][0], sb + b_frag0 + ko);
            ldm_x4(BL[kk2][0], sb + b_frag0 + ko + B_HL);
            ldm_x4(BH[kk2][1], sb + b_frag1 + ko);
            ldm_x4(BL[kk2][1], sb + b_frag1 + ko + B_HL);
        }

        // 24-MMA burst; rounds cycle the 4 accumulator chains for ILP
        #pragma unroll
        for (int kk2 = 0; kk2 < 2; kk2++) {
            #pragma unroll
            for (int t3 = 0; t3 < 3; t3++) {
                const uint32_t* a = (t3 == 2) ? AL[kk2] : AH[kk2];
                #pragma unroll
                for (int p = 0; p < 2; p++) {
                    const uint32_t* b = (t3 == 1) ? BL[kk2][p] : BH[kk2][p];
                    mma_bf16(acc[2 * p],     a, b[0], b[1]);
                    mma_bf16(acc[2 * p + 1], a, b[2], b[3]);
                }
            }
        }
    }
    __syncthreads();   // all MMAs done before z_s aliases stage memory

    // ---- spill accs to smem (aliased over dead pipeline stages) ----
    {
        const int row_l = wm + gid;
        #pragma unroll
        for (int nf = 0; nf < 4; nf++) {
            const int col = wn + nf * 8 + 2 * tig;
            *(float2*)&z_s[row_l * ZPAD + col] =
                make_float2(acc[nf][0], acc[nf][1]);
            *(float2*)&z_s[(row_l + 8) * ZPAD + col] =
                make_float2(acc[nf][2], acc[nf][3]);
        }
    }
    __syncthreads();

    // ---- fused pointwise: x-proj + bias + activations + c/h update ----
    #pragma unroll
    for (int rep = 0; rep < (GBM * JB) / NT; rep++) {   // 4 reps
        const int elem = tid + rep * NT;
        const int r = elem >> 4, jl = elem & 15;
        const int gr = bb + r, gj = bj + jl;

        float zg = z_s[r * ZPAD + 4 * jl + 0] + bias_s[0 * JB + jl];
        float zi = z_s[r * ZPAD + 4 * jl + 1] + bias_s[1 * JB + jl];
        float zf = z_s[r * ZPAD + 4 * jl + 2] + bias_s[2 * JB + jl];
        float zo = z_s[r * ZPAD + 4 * jl + 3] + bias_s[3 * JB + jl];

        #pragma unroll
        for (int e = 0; e < E_; e++) {
            float xv = xe_s[r * E_ + e];
            zg += xv * xw_s[0 * E_ * JB + e * JB + jl];
            zi += xv * xw_s[1 * E_ * JB + e * JB + jl];
            zf += xv * xw_s[2 * E_ * JB + e * JB + jl];
            zo += xv * xw_s[3 * E_ * JB + e * JB + jl];
        }

        float gg = tanhf(zg);
        float ii = 1.0f / (1.0f + __expf(-zi));
        float ff = 1.0f / (1.0f + __expf(-zf));
        float oo = 1.0f / (1.0f + __expf(-zo));

        float cn = gg * ii + g_c[gr * H_ + gj] * ff;
        float hn = tanhf(cn) * oo;

        g_c[gr * H_ + gj] = cn;
        __nv_bfloat16 hi = __float2bfloat16(hn);
        hhi_out[gr * H_ + gj] = hi;
        hlo_out[gr * H_ + gj] = __float2bfloat16(hn - __bfloat162float(hi));
    }
}

// ---------------------------------------------------------------------------
// Final projection: h reconstructed as hi+lo from buffer 0 (after t=255).
// ---------------------------------------------------------------------------
__global__ void proj_kernel(const float* __restrict__ Wph,
                            const float* __restrict__ bp, float* __restrict__ out) {
    int i = blockIdx.x * blockDim.x + threadIdx.x;
    if (i >= B_ * C_) return;
    int b = i / C_;
    int c = i % C_;
    float acc = bp[c];
    #pragma unroll 8
    for (int k = 0; k < H_; k++) {
        float h = __bfloat162float(g_hhi[0][b * H_ + k]) +
                  __bfloat162float(g_hlo[0][b * H_ + k]);
        acc += h * Wph[k * C_ + c];
    }
    out[i] = acc;
}

// ---------------------------------------------------------------------------
// Launch sequence (graph-capturable, single stream)
// ---------------------------------------------------------------------------
extern "C" void kernel_launch(void* const* d_in, const int* in_sizes, int n_in,
                              void* d_out, int out_size) {
    const int* x        = (const int*)d_in[0];       // int32 (JAX downcasts int64)
    const float* emb    = (const float*)d_in[1];
    const float* Wgx    = (const float*)d_in[2];
    const float* Wgh    = (const float*)d_in[3];
    const float* bg     = (const float*)d_in[4];
    const float* Wix    = (const float*)d_in[5];
    const float* Wih    = (const float*)d_in[6];
    const float* bi     = (const float*)d_in[7];
    const float* Wfx    = (const float*)d_in[8];
    const float* Wfh    = (const float*)d_in[9];
    const float* bf_    = (const float*)d_in[10];
    const float* Wox    = (const float*)d_in[11];
    const float* Woh    = (const float*)d_in[12];
    const float* bo     = (const float*)d_in[13];
    const float* Wph    = (const float*)d_in[14];
    const float* bp     = (const float*)d_in[15];
    float* out          = (float*)d_out;

    static bool attr_set = false;
    if (!attr_set) {
        cudaFuncSetAttribute(lstm_fused_step,
                             cudaFuncAttributeMaxDynamicSharedMemorySize,
                             FUSED_SMEM_BYTES);
        attr_set = true;
    }

    {
        dim3 tgrid(H_ / 32, H_ / 32, NGATE);
        dim3 tblk(32, 32);
        prep_weights_kernel<<<tgrid, tblk>>>(Wgh, Wih, Wfh, Woh);
    }
    init_state_kernel<<<(B_ * H_ + 255) / 256, 256>>>();

    dim3 ggrid(N_TOT / GBN, B_ / GBM);   // (32, 8) = 256 blocks
    for (int t = 0; t < T_; t++) {
        lstm_fused_step<<<ggrid, NT, FUSED_SMEM_BYTES>>>(
            t, t & 1, x, emb, Wgx, Wix, Wfx, Wox, bg, bi, bf_, bo);
    }

    proj_kernel<<<(B_ * C_ + 255) / 256, 256>>>(Wph, bp, out);
}

// round 11
// speedup vs baseline: 1.3495x; 1.3055x over previous
#include <cuda_runtime.h>
#include <cuda_fp16.h>
#include <math.h>
#include <stdint.h>

// Problem constants
#define B_ 512
#define T_ 256
#define H_ 512
#define E_ 10
#define V_ 10000
#define C_ 10
#define NGATE 4
#define N_TOT (NGATE * H_)   // 2048; layout n = 4*j + gate (gates interleaved)

// ---------------------------------------------------------------------------
// Device-global state & scratch (no allocations allowed)
// h is kept as a 2xfp16 split (hi+lo ~ 22-bit effective state, exact-ish);
// W is a single fp16 (one-time rounding, rel ~2.8e-4 rms; empirically <1x
// amplified through the recurrence).
// ---------------------------------------------------------------------------
__device__ float g_c[B_ * H_];
__device__ __half g_hhi[2][B_ * H_];   // ping-pong (cross-block hazard)
__device__ __half g_hlo[2][B_ * H_];
__device__ __half g_Wt[N_TOT * H_];    // W^T fp16: [n=4j+g][k]

// ---------------------------------------------------------------------------
// One-time weight transpose + fp16 round: g_Wt[(4j+g)][k] = fp16(Wh_g[k][j])
// ---------------------------------------------------------------------------
__global__ void prep_weights_kernel(
    const float* __restrict__ Wgh, const float* __restrict__ Wih,
    const float* __restrict__ Wfh, const float* __restrict__ Woh)
{
    int idx = blockIdx.x * 256 + threadIdx.x;   // over 2048*512
    int n = idx >> 9;
    int k = idx & 511;
    int g = n & 3;
    int j = n >> 2;
    const float* const W[4] = {Wgh, Wih, Wfh, Woh};
    g_Wt[n * H_ + k] = __float2half(W[g][k * H_ + j]);
}

__global__ void init_state_kernel() {
    int i = blockIdx.x * blockDim.x + threadIdx.x;
    if (i < B_ * H_) {
        g_c[i] = 0.0f;
        g_hhi[0][i] = __float2half(0.0f);
        g_hlo[0][i] = __float2half(0.0f);
    }
}

__device__ __forceinline__ void cp16(void* smem_dst, const void* gmem_src) {
    uint32_t s = (uint32_t)__cvta_generic_to_shared(smem_dst);
    asm volatile("cp.async.cg.shared.global [%0], [%1], 16;" :: "r"(s), "l"(gmem_src));
}

__device__ __forceinline__ void ldm_x4(uint32_t r[4], uint32_t addr) {
    asm volatile("ldmatrix.sync.aligned.m8n8.x4.shared.b16 {%0,%1,%2,%3}, [%4];"
                 : "=r"(r[0]), "=r"(r[1]), "=r"(r[2]), "=r"(r[3]) : "r"(addr));
}

__device__ __forceinline__ void mma_f16(
    float c[4], const uint32_t a[4], uint32_t b0, uint32_t b1)
{
    asm volatile(
        "mma.sync.aligned.m16n8k16.row.col.f32.f16.f16.f32 "
        "{%0,%1,%2,%3}, {%4,%5,%6,%7}, {%8,%9}, {%0,%1,%2,%3};"
        : "+f"(c[0]), "+f"(c[1]), "+f"(c[2]), "+f"(c[3])
        : "r"(a[0]), "r"(a[1]), "r"(a[2]), "r"(a[3]), "r"(b0), "r"(b1));
}

// ---------------------------------------------------------------------------
// Fully fused LSTM step. Block tile 64(M) x 64(N = 16 j x 4 gates),
// 8 warps (warp tile 16x32), k-chunks of 32, 3-stage cp.async pipeline,
// hoisted ldmatrix, 2-term fp16 MMA (h split hi/lo, W single).
// Grid (2048/64, 512/64) = (32, 8) = 256 blocks.
// ---------------------------------------------------------------------------
#define GBM 64
#define GBN 64
#define GKC 32
#define APAD 40
#define NT 256
#define STAGES 3
#define A_STAGE_BYTES (2 * GBM * APAD * 2)      // hi+lo: 10240 B
#define B_STAGE_BYTES (GBN * APAD * 2)          // single: 5120 B
#define STAGE_BYTES (A_STAGE_BYTES + B_STAGE_BYTES)   // 15360 B
#define A_OFF 0
#define B_OFF A_STAGE_BYTES
#define A_HL (GBM * APAD * 2)                   // 5120 B
#define MAIN_SMEM_BYTES (STAGES * STAGE_BYTES)  // 46080 B
#define JB (GBN / NGATE)                        // 16 j per block
#define ZPAD 68
#define EXTRA_FLOATS (GBM * E_ + NGATE * E_ * JB + NGATE * JB)  // 1344
#define FUSED_SMEM_BYTES (MAIN_SMEM_BYTES + EXTRA_FLOATS * 4)   // 51456 B

__global__ void __launch_bounds__(NT, 2) lstm_fused_step(
    int t, int src,
    const int* __restrict__ x, const float* __restrict__ emb,
    const float* __restrict__ Wgx, const float* __restrict__ Wix,
    const float* __restrict__ Wfx, const float* __restrict__ Wox,
    const float* __restrict__ bg, const float* __restrict__ bi,
    const float* __restrict__ bf_, const float* __restrict__ bo)
{
    extern __shared__ char smem_raw[];
    float* const z_s    = (float*)smem_raw;                     // epilogue alias
    float* const xe_s   = (float*)(smem_raw + MAIN_SMEM_BYTES); // [64][E_]
    float* const xw_s   = xe_s + GBM * E_;                      // [4][E_][JB]
    float* const bias_s = xw_s + NGATE * E_ * JB;               // [4][JB]

    const int tid = threadIdx.x;
    const int bn = blockIdx.x * GBN;    // col base (n = 4j+g)
    const int bj = blockIdx.x * JB;     // j base
    const int bb = blockIdx.y * GBM;    // batch base
    const int w = tid >> 5;
    const int lane = tid & 31;
    const int gid = lane >> 2;
    const int tig = lane & 3;
    const int wm = (w >> 1) * 16;       // 4 m-groups
    const int wn = (w & 1) * 32;        // 2 n-groups

    const __half* __restrict__ hhi = g_hhi[src];
    const __half* __restrict__ hlo = g_hlo[src];
    __half* __restrict__ hhi_out = g_hhi[src ^ 1];
    __half* __restrict__ hlo_out = g_hlo[src ^ 1];

    const uint32_t SBase = (uint32_t)__cvta_generic_to_shared(smem_raw);

    // per-lane ldmatrix fragment offsets (bytes, relative to stage base)
    const uint32_t a_frag = A_OFF +
        ((wm + ((lane >> 3) & 1) * 8 + (lane & 7)) * APAD + ((lane >> 4) & 1) * 8) * 2;
    const uint32_t b_frag0 = B_OFF +
        ((wn + ((lane >> 4) & 1) * 8 + (lane & 7)) * APAD + ((lane >> 3) & 1) * 8) * 2;
    const uint32_t b_frag1 = b_frag0 + 16 * APAD * 2;   // +16 n rows

    char* const smem_c = smem_raw;

    auto load_chunk = [&](int stage, int k0) {
        char* sb = smem_c + stage * STAGE_BYTES;
        // A: 2hl * 64r * 32k fp16 = 512 x 16B segs -> 2 per thread
        #pragma unroll
        for (int half = 0; half < 2; half++) {
            int idx = tid + half * NT;
            int hl = idx >> 8, r = (idx >> 2) & 63, s = (idx & 3) * 8;
            const __half* srcp = hl ? hlo : hhi;
            cp16(sb + A_OFF + hl * A_HL + (r * APAD + s) * 2,
                 &srcp[(bb + r) * H_ + k0 + s]);
        }
        // B: 64r * 32k = 256 segs -> 1 per thread
        {
            int br = tid >> 2, bs = (tid & 3) * 8;
            cp16(sb + B_OFF + (br * APAD + bs) * 2,
                 &g_Wt[(bn + br) * H_ + k0 + bs]);
        }
        asm volatile("cp.async.commit_group;");
    };

    // prologue: 2 chunks in flight
    load_chunk(0, 0);
    load_chunk(1, GKC);

    // ---- stage epilogue operands (disjoint smem; overlaps pipeline) ----
    for (int i = tid; i < GBM * E_; i += NT) {
        int r = i / E_, e = i % E_;
        int idx = x[(bb + r) * T_ + t];
        idx = min(max(idx, 0), V_ - 1);
        xe_s[r * E_ + e] = emb[idx * E_ + e];
    }
    {
        const float* const Wx[4] = {Wgx, Wix, Wfx, Wox};
        for (int i = tid; i < NGATE * E_ * JB; i += NT) {
            int g = i / (E_ * JB), rem = i % (E_ * JB);
            int e = rem / JB, jl = rem % JB;
            xw_s[i] = Wx[g][e * H_ + bj + jl];
        }
        const float* const bptr[4] = {bg, bi, bf_, bo};
        if (tid < NGATE * JB) {
            int g = tid / JB, jl = tid % JB;
            bias_s[tid] = bptr[g][bj + jl];
        }
    }

    float acc[4][4];
    #pragma unroll
    for (int nf = 0; nf < 4; nf++)
        #pragma unroll
        for (int v = 0; v < 4; v++) acc[nf][v] = 0.0f;

    // ---- recurrent GEMM mainloop: 16 chunks, 3-stage pipeline ----
    const int NCH = H_ / GKC;   // 16
    #pragma unroll 1
    for (int kt = 0; kt < NCH; kt++) {
        if (kt < NCH - 2) {
            asm volatile("cp.async.wait_group 1;" ::: "memory");
        } else {
            asm volatile("cp.async.wait_group 0;" ::: "memory");
        }
        __syncthreads();                       // chunk kt visible to all warps
        if (kt + 2 < NCH) load_chunk((kt + 2) % STAGES, (kt + 2) * GKC);

        const uint32_t sb = SBase + (kt % STAGES) * STAGE_BYTES;

        // hoisted fragment loads: 8 ldmatrix for the whole chunk
        uint32_t AH[2][4], AL[2][4], BV[2][2][4];
        #pragma unroll
        for (int kk2 = 0; kk2 < 2; kk2++) {
            const uint32_t ko = kk2 * 32;      // 16 fp16 = 32 bytes
            ldm_x4(AH[kk2], sb + a_frag + ko);
            ldm_x4(AL[kk2], sb + a_frag + ko + A_HL);
            ldm_x4(BV[kk2][0], sb + b_frag0 + ko);
            ldm_x4(BV[kk2][1], sb + b_frag1 + ko);
        }

        // 16-MMA burst; rounds cycle the 4 accumulator chains for ILP
        #pragma unroll
        for (int kk2 = 0; kk2 < 2; kk2++) {
            #pragma unroll
            for (int t2 = 0; t2 < 2; t2++) {
                const uint32_t* a = (t2 == 0) ? AH[kk2] : AL[kk2];
                #pragma unroll
                for (int p = 0; p < 2; p++) {
                    const uint32_t* b = BV[kk2][p];
                    mma_f16(acc[2 * p],     a, b[0], b[1]);
                    mma_f16(acc[2 * p + 1], a, b[2], b[3]);
                }
            }
        }
    }
    __syncthreads();   // all MMAs done before z_s aliases stage memory

    // ---- spill accs to smem (aliased over dead pipeline stages) ----
    {
        const int row_l = wm + gid;
        #pragma unroll
        for (int nf = 0; nf < 4; nf++) {
            const int col = wn + nf * 8 + 2 * tig;
            *(float2*)&z_s[row_l * ZPAD + col] =
                make_float2(acc[nf][0], acc[nf][1]);
            *(float2*)&z_s[(row_l + 8) * ZPAD + col] =
                make_float2(acc[nf][2], acc[nf][3]);
        }
    }
    __syncthreads();

    // ---- fused pointwise: x-proj + bias + activations + c/h update ----
    #pragma unroll
    for (int rep = 0; rep < (GBM * JB) / NT; rep++) {   // 4 reps
        const int elem = tid + rep * NT;
        const int r = elem >> 4, jl = elem & 15;
        const int gr = bb + r, gj = bj + jl;

        float zg = z_s[r * ZPAD + 4 * jl + 0] + bias_s[0 * JB + jl];
        float zi = z_s[r * ZPAD + 4 * jl + 1] + bias_s[1 * JB + jl];
        float zf = z_s[r * ZPAD + 4 * jl + 2] + bias_s[2 * JB + jl];
        float zo = z_s[r * ZPAD + 4 * jl + 3] + bias_s[3 * JB + jl];

        #pragma unroll
        for (int e = 0; e < E_; e++) {
            float xv = xe_s[r * E_ + e];
            zg += xv * xw_s[0 * E_ * JB + e * JB + jl];
            zi += xv * xw_s[1 * E_ * JB + e * JB + jl];
            zf += xv * xw_s[2 * E_ * JB + e * JB + jl];
            zo += xv * xw_s[3 * E_ * JB + e * JB + jl];
        }

        float gg = tanhf(zg);
        float ii = 1.0f / (1.0f + __expf(-zi));
        float ff = 1.0f / (1.0f + __expf(-zf));
        float oo = 1.0f / (1.0f + __expf(-zo));

        float cn = gg * ii + g_c[gr * H_ + gj] * ff;
        float hn = tanhf(cn) * oo;

        g_c[gr * H_ + gj] = cn;
        __half hi = __float2half(hn);
        hhi_out[gr * H_ + gj] = hi;
        hlo_out[gr * H_ + gj] = __float2half(hn - __half2float(hi));
    }
}

// ---------------------------------------------------------------------------
// Final projection: h reconstructed as hi+lo from buffer 0 (after t=255).
// ---------------------------------------------------------------------------
__global__ void proj_kernel(const float* __restrict__ Wph,
                            const float* __restrict__ bp, float* __restrict__ out) {
    int i = blockIdx.x * blockDim.x + threadIdx.x;
    if (i >= B_ * C_) return;
    int b = i / C_;
    int c = i % C_;
    float acc = bp[c];
    #pragma unroll 8
    for (int k = 0; k < H_; k++) {
        float h = __half2float(g_hhi[0][b * H_ + k]) +
                  __half2float(g_hlo[0][b * H_ + k]);
        acc += h * Wph[k * C_ + c];
    }
    out[i] = acc;
}

// ---------------------------------------------------------------------------
// Launch sequence (graph-capturable, single stream)
// ---------------------------------------------------------------------------
extern "C" void kernel_launch(void* const* d_in, const int* in_sizes, int n_in,
                              void* d_out, int out_size) {
    const int* x        = (const int*)d_in[0];       // int32 (JAX downcasts int64)
    const float* emb    = (const float*)d_in[1];
    const float* Wgx    = (const float*)d_in[2];
    const float* Wgh    = (const float*)d_in[3];
    const float* bg     = (const float*)d_in[4];
    const float* Wix    = (const float*)d_in[5];
    const float* Wih    = (const float*)d_in[6];
    const float* bi     = (const float*)d_in[7];
    const float* Wfx    = (const float*)d_in[8];
    const float* Wfh    = (const float*)d_in[9];
    const float* bf_    = (const float*)d_in[10];
    const float* Wox    = (const float*)d_in[11];
    const float* Woh    = (const float*)d_in[12];
    const float* bo     = (const float*)d_in[13];
    const float* Wph    = (const float*)d_in[14];
    const float* bp     = (const float*)d_in[15];
    float* out          = (float*)d_out;

    static bool attr_set = false;
    if (!attr_set) {
        cudaFuncSetAttribute(lstm_fused_step,
                             cudaFuncAttributeMaxDynamicSharedMemorySize,
                             FUSED_SMEM_BYTES);
        attr_set = true;
    }

    prep_weights_kernel<<<(N_TOT * H_) / 256, 256>>>(Wgh, Wih, Wfh, Woh);
    init_state_kernel<<<(B_ * H_ + 255) / 256, 256>>>();

    dim3 ggrid(N_TOT / GBN, B_ / GBM);   // (32, 8) = 256 blocks
    for (int t = 0; t < T_; t++) {
        lstm_fused_step<<<ggrid, NT, FUSED_SMEM_BYTES>>>(
            t, t & 1, x, emb, Wgx, Wix, Wfx, Wox, bg, bi, bf_, bo);
    }

    proj_kernel<<<(B_ * C_ + 255) / 256, 256>>>(Wph, bp, out);
}

// round 12
// speedup vs baseline: 1.3926x; 1.0319x over previous
#include <cuda_runtime.h>
#include <cuda_fp16.h>
#include <math.h>
#include <stdint.h>

// Problem constants
#define B_ 512
#define T_ 256
#define H_ 512
#define E_ 10
#define V_ 10000
#define C_ 10
#define NGATE 4
#define N_TOT (NGATE * H_)   // 2048; layout n = 4*j + gate (gates interleaved)

// ---------------------------------------------------------------------------
// Device-global state & scratch (no allocations allowed)
// h and W both single fp16 (1-term MMA). h fp16 rounding injects ~2^-12
// rel/step; W rounding alone measured 7.7e-5 final -> combined ~1.5e-4.
// ---------------------------------------------------------------------------
__device__ float g_c[B_ * H_];
__device__ __half g_hh[2][B_ * H_];    // ping-pong (cross-block hazard)
__device__ __half g_Wt[N_TOT * H_];    // W^T fp16: [n=4j+g][k]

// ---------------------------------------------------------------------------
// One-time weight transpose + fp16 round: g_Wt[(4j+g)][k] = fp16(Wh_g[k][j])
// ---------------------------------------------------------------------------
__global__ void prep_weights_kernel(
    const float* __restrict__ Wgh, const float* __restrict__ Wih,
    const float* __restrict__ Wfh, const float* __restrict__ Woh)
{
    int idx = blockIdx.x * 256 + threadIdx.x;   // over 2048*512
    int n = idx >> 9;
    int k = idx & 511;
    int g = n & 3;
    int j = n >> 2;
    const float* const W[4] = {Wgh, Wih, Wfh, Woh};
    g_Wt[n * H_ + k] = __float2half(W[g][k * H_ + j]);
}

__global__ void init_state_kernel() {
    int i = blockIdx.x * blockDim.x + threadIdx.x;
    if (i < B_ * H_) {
        g_c[i] = 0.0f;
        g_hh[0][i] = __float2half(0.0f);
    }
}

__device__ __forceinline__ void cp16(void* smem_dst, const void* gmem_src) {
    uint32_t s = (uint32_t)__cvta_generic_to_shared(smem_dst);
    asm volatile("cp.async.cg.shared.global [%0], [%1], 16;" :: "r"(s), "l"(gmem_src));
}

__device__ __forceinline__ void ldm_x4(uint32_t r[4], uint32_t addr) {
    asm volatile("ldmatrix.sync.aligned.m8n8.x4.shared.b16 {%0,%1,%2,%3}, [%4];"
                 : "=r"(r[0]), "=r"(r[1]), "=r"(r[2]), "=r"(r[3]) : "r"(addr));
}

__device__ __forceinline__ void mma_f16(
    float c[4], const uint32_t a[4], uint32_t b0, uint32_t b1)
{
    asm volatile(
        "mma.sync.aligned.m16n8k16.row.col.f32.f16.f16.f32 "
        "{%0,%1,%2,%3}, {%4,%5,%6,%7}, {%8,%9}, {%0,%1,%2,%3};"
        : "+f"(c[0]), "+f"(c[1]), "+f"(c[2]), "+f"(c[3])
        : "r"(a[0]), "r"(a[1]), "r"(a[2]), "r"(a[3]), "r"(b0), "r"(b1));
}

// ---------------------------------------------------------------------------
// Fully fused LSTM step. Block tile 64(M) x 64(N = 16 j x 4 gates),
// 16 warps (warp tile 16x16 -> 4 MMA/chunk/warp), k-chunks of 32, 3-stage
// cp.async pipeline, 1-term fp16 MMA. Small 36KB footprint -> 2 blocks/SM,
// 8 warps/SMSP: independent block barriers fill each other's bubbles.
// Grid (2048/64, 512/64) = (32, 8) = 256 blocks.
// ---------------------------------------------------------------------------
#define GBM 64
#define GBN 64
#define GKC 32
#define APAD 40
#define NT 512
#define STAGES 3
#define A_STAGE_BYTES (GBM * APAD * 2)          // 5120 B
#define B_STAGE_BYTES (GBN * APAD * 2)          // 5120 B
#define STAGE_BYTES (A_STAGE_BYTES + B_STAGE_BYTES)   // 10240 B
#define A_OFF 0
#define B_OFF A_STAGE_BYTES
#define MAIN_SMEM_BYTES (STAGES * STAGE_BYTES)  // 30720 B
#define JB (GBN / NGATE)                        // 16 j per block
#define ZPAD 68
#define EXTRA_FLOATS (GBM * E_ + NGATE * E_ * JB + NGATE * JB)  // 1344
#define FUSED_SMEM_BYTES (MAIN_SMEM_BYTES + EXTRA_FLOATS * 4)   // 36096 B

__global__ void __launch_bounds__(NT, 2) lstm_fused_step(
    int t, int src,
    const int* __restrict__ x, const float* __restrict__ emb,
    const float* __restrict__ Wgx, const float* __restrict__ Wix,
    const float* __restrict__ Wfx, const float* __restrict__ Wox,
    const float* __restrict__ bg, const float* __restrict__ bi,
    const float* __restrict__ bf_, const float* __restrict__ bo)
{
    extern __shared__ char smem_raw[];
    float* const z_s    = (float*)smem_raw;                     // epilogue alias
    float* const xe_s   = (float*)(smem_raw + MAIN_SMEM_BYTES); // [64][E_]
    float* const xw_s   = xe_s + GBM * E_;                      // [4][E_][JB]
    float* const bias_s = xw_s + NGATE * E_ * JB;               // [4][JB]

    const int tid = threadIdx.x;
    const int bn = blockIdx.x * GBN;    // col base (n = 4j+g)
    const int bj = blockIdx.x * JB;     // j base
    const int bb = blockIdx.y * GBM;    // batch base
    const int w = tid >> 5;
    const int lane = tid & 31;
    const int gid = lane >> 2;
    const int tig = lane & 3;
    const int wm = (w >> 2) * 16;       // 4 m-groups of 16
    const int wn = (w & 3) * 16;        // 4 n-groups of 16

    const __half* __restrict__ hh = g_hh[src];
    __half* __restrict__ hh_out = g_hh[src ^ 1];

    const uint32_t SBase = (uint32_t)__cvta_generic_to_shared(smem_raw);

    // per-lane ldmatrix fragment offsets (bytes, relative to stage base)
    const uint32_t a_frag = A_OFF +
        ((wm + ((lane >> 3) & 1) * 8 + (lane & 7)) * APAD + ((lane >> 4) & 1) * 8) * 2;
    const uint32_t b_frag = B_OFF +
        ((wn + ((lane >> 4) & 1) * 8 + (lane & 7)) * APAD + ((lane >> 3) & 1) * 8) * 2;

    char* const smem_c = smem_raw;

    auto load_chunk = [&](int stage, int k0) {
        char* sb = smem_c + stage * STAGE_BYTES;
        if (tid < 256) {
            // A: 64r * 32k fp16 = 256 x 16B segs
            int r = tid >> 2, s = (tid & 3) * 8;
            cp16(sb + A_OFF + (r * APAD + s) * 2, &hh[(bb + r) * H_ + k0 + s]);
        } else {
            // B: 64r * 32k = 256 segs
            int i2 = tid - 256;
            int br = i2 >> 2, bs = (i2 & 3) * 8;
            cp16(sb + B_OFF + (br * APAD + bs) * 2, &g_Wt[(bn + br) * H_ + k0 + bs]);
        }
        asm volatile("cp.async.commit_group;");
    };

    // prologue: 2 chunks in flight
    load_chunk(0, 0);
    load_chunk(1, GKC);

    // ---- stage epilogue operands (disjoint smem; overlaps pipeline) ----
    for (int i = tid; i < GBM * E_; i += NT) {
        int r = i / E_, e = i % E_;
        int idx = x[(bb + r) * T_ + t];
        idx = min(max(idx, 0), V_ - 1);
        xe_s[r * E_ + e] = emb[idx * E_ + e];
    }
    {
        const float* const Wx[4] = {Wgx, Wix, Wfx, Wox};
        for (int i = tid; i < NGATE * E_ * JB; i += NT) {
            int g = i / (E_ * JB), rem = i % (E_ * JB);
            int e = rem / JB, jl = rem % JB;
            xw_s[i] = Wx[g][e * H_ + bj + jl];
        }
        const float* const bptr[4] = {bg, bi, bf_, bo};
        if (tid < NGATE * JB) {
            int g = tid / JB, jl = tid % JB;
            bias_s[tid] = bptr[g][bj + jl];
        }
    }

    float acc[2][4];
    #pragma unroll
    for (int nf = 0; nf < 2; nf++)
        #pragma unroll
        for (int v = 0; v < 4; v++) acc[nf][v] = 0.0f;

    // ---- recurrent GEMM mainloop: 16 chunks, 3-stage pipeline ----
    const int NCH = H_ / GKC;   // 16
    #pragma unroll 1
    for (int kt = 0; kt < NCH; kt++) {
        if (kt < NCH - 2) {
            asm volatile("cp.async.wait_group 1;" ::: "memory");
        } else {
            asm volatile("cp.async.wait_group 0;" ::: "memory");
        }
        __syncthreads();                       // chunk kt visible to all warps
        if (kt + 2 < NCH) load_chunk((kt + 2) % STAGES, (kt + 2) * GKC);

        const uint32_t sb = SBase + (kt % STAGES) * STAGE_BYTES;

        // 4 ldmatrix + 8 MMA per chunk per warp
        uint32_t AV[2][4], BV[2][4];
        #pragma unroll
        for (int kk2 = 0; kk2 < 2; kk2++) {
            const uint32_t ko = kk2 * 32;      // 16 fp16 = 32 bytes
            ldm_x4(AV[kk2], sb + a_frag + ko);
            ldm_x4(BV[kk2], sb + b_frag + ko);
        }
        #pragma unroll
        for (int kk2 = 0; kk2 < 2; kk2++) {
            mma_f16(acc[0], AV[kk2], BV[kk2][0], BV[kk2][1]);
            mma_f16(acc[1], AV[kk2], BV[kk2][2], BV[kk2][3]);
        }
    }
    __syncthreads();   // all MMAs done before z_s aliases stage memory

    // ---- spill accs to smem (aliased over dead pipeline stages) ----
    {
        const int row_l = wm + gid;
        #pragma unroll
        for (int nf = 0; nf < 2; nf++) {
            const int col = wn + nf * 8 + 2 * tig;
            *(float2*)&z_s[row_l * ZPAD + col] =
                make_float2(acc[nf][0], acc[nf][1]);
            *(float2*)&z_s[(row_l + 8) * ZPAD + col] =
                make_float2(acc[nf][2], acc[nf][3]);
        }
    }
    __syncthreads();

    // ---- fused pointwise: x-proj + bias + activations + c/h update ----
    #pragma unroll
    for (int rep = 0; rep < (GBM * JB) / NT; rep++) {   // 2 reps
        const int elem = tid + rep * NT;
        const int r = elem >> 4, jl = elem & 15;
        const int gr = bb + r, gj = bj + jl;

        float zg = z_s[r * ZPAD + 4 * jl + 0] + bias_s[0 * JB + jl];
        float zi = z_s[r * ZPAD + 4 * jl + 1] + bias_s[1 * JB + jl];
        float zf = z_s[r * ZPAD + 4 * jl + 2] + bias_s[2 * JB + jl];
        float zo = z_s[r * ZPAD + 4 * jl + 3] + bias_s[3 * JB + jl];

        #pragma unroll
        for (int e = 0; e < E_; e++) {
            float xv = xe_s[r * E_ + e];
            zg += xv * xw_s[0 * E_ * JB + e * JB + jl];
            zi += xv * xw_s[1 * E_ * JB + e * JB + jl];
            zf += xv * xw_s[2 * E_ * JB + e * JB + jl];
            zo += xv * xw_s[3 * E_ * JB + e * JB + jl];
        }

        float gg = tanhf(zg);
        float ii = 1.0f / (1.0f + __expf(-zi));
        float ff = 1.0f / (1.0f + __expf(-zf));
        float oo = 1.0f / (1.0f + __expf(-zo));

        float cn = gg * ii + g_c[gr * H_ + gj] * ff;
        float hn = tanhf(cn) * oo;

        g_c[gr * H_ + gj] = cn;
        hh_out[gr * H_ + gj] = __float2half(hn);
    }
}

// ---------------------------------------------------------------------------
// Final projection: h from fp16 buffer 0 (after t=255).
// ---------------------------------------------------------------------------
__global__ void proj_kernel(const float* __restrict__ Wph,
                            const float* __restrict__ bp, float* __restrict__ out) {
    int i = blockIdx.x * blockDim.x + threadIdx.x;
    if (i >= B_ * C_) return;
    int b = i / C_;
    int c = i % C_;
    float acc = bp[c];
    #pragma unroll 8
    for (int k = 0; k < H_; k++) {
        acc += __half2float(g_hh[0][b * H_ + k]) * Wph[k * C_ + c];
    }
    out[i] = acc;
}

// ---------------------------------------------------------------------------
// Launch sequence (graph-capturable, single stream)
// ---------------------------------------------------------------------------
extern "C" void kernel_launch(void* const* d_in, const int* in_sizes, int n_in,
                              void* d_out, int out_size) {
    const int* x        = (const int*)d_in[0];       // int32 (JAX downcasts int64)
    const float* emb    = (const float*)d_in[1];
    const float* Wgx    = (const float*)d_in[2];
    const float* Wgh    = (const float*)d_in[3];
    const float* bg     = (const float*)d_in[4];
    const float* Wix    = (const float*)d_in[5];
    const float* Wih    = (const float*)d_in[6];
    const float* bi     = (const float*)d_in[7];
    const float* Wfx    = (const float*)d_in[8];
    const float* Wfh    = (const float*)d_in[9];
    const float* bf_    = (const float*)d_in[10];
    const float* Wox    = (const float*)d_in[11];
    const float* Woh    = (const float*)d_in[12];
    const float* bo     = (const float*)d_in[13];
    const float* Wph    = (const float*)d_in[14];
    const float* bp     = (const float*)d_in[15];
    float* out          = (float*)d_out;

    static bool attr_set = false;
    if (!attr_set) {
        cudaFuncSetAttribute(lstm_fused_step,
                             cudaFuncAttributeMaxDynamicSharedMemorySize,
                             FUSED_SMEM_BYTES);
        attr_set = true;
    }

    prep_weights_kernel<<<(N_TOT * H_) / 256, 256>>>(Wgh, Wih, Wfh, Woh);
    init_state_kernel<<<(B_ * H_ + 255) / 256, 256>>>();

    dim3 ggrid(N_TOT / GBN, B_ / GBM);   // (32, 8) = 256 blocks
    for (int t = 0; t < T_; t++) {
        lstm_fused_step<<<ggrid, NT, FUSED_SMEM_BYTES>>>(
            t, t & 1, x, emb, Wgx, Wix, Wfx, Wox, bg, bi, bf_, bo);
    }

    proj_kernel<<<(B_ * C_ + 255) / 256, 256>>>(Wph, bp, out);
}

// round 13
// speedup vs baseline: 1.8260x; 1.3112x over previous
#include <cuda_runtime.h>
#include <cuda_fp16.h>
#include <math.h>
#include <stdint.h>

// Problem constants
#define B_ 512
#define T_ 256
#define H_ 512
#define E_ 10
#define V_ 10000
#define C_ 10
#define NGATE 4
#define N_TOT (NGATE * H_)   // 2048; layout n = 4*j + gate (gates interleaved)

#define NBLK 128             // persistent blocks: 1 per SM guaranteed (smem)
#define NT 512

// ---------------------------------------------------------------------------
// Device globals (no allocations allowed)
// ---------------------------------------------------------------------------
__device__ float g_c[B_ * H_];
__device__ __half g_hh[2][B_ * H_];    // ping-pong recurrent state (fp16)
__device__ __half g_Wt[N_TOT * H_];    // W^T fp16: [n=4j+g][k]
__device__ float g_xef[T_ * B_ * 16];  // pre-gathered emb[x], padded to 16
__device__ volatile unsigned g_flags[NBLK];
__device__ volatile unsigned g_gen;

// ---------------------------------------------------------------------------
// One-time preps
// ---------------------------------------------------------------------------
__global__ void prep_weights_kernel(
    const float* __restrict__ Wgh, const float* __restrict__ Wih,
    const float* __restrict__ Wfh, const float* __restrict__ Woh)
{
    int idx = blockIdx.x * 256 + threadIdx.x;   // over 2048*512
    int n = idx >> 9;
    int k = idx & 511;
    int g = n & 3;
    int j = n >> 2;
    const float* const W[4] = {Wgh, Wih, Wfh, Woh};
    g_Wt[n * H_ + k] = __float2half(W[g][k * H_ + j]);
}

__global__ void prep_xe_kernel(const int* __restrict__ x,
                               const float* __restrict__ emb) {
    int idx = blockIdx.x * 256 + threadIdx.x;   // over T*B*16 = 2M
    int t = idx >> 13;           // B*16 = 8192
    int b = (idx >> 4) & (B_ - 1);
    int e = idx & 15;
    float v = 0.0f;
    if (e < E_) {
        int tok = x[b * T_ + t];
        tok = min(max(tok, 0), V_ - 1);
        v = emb[tok * E_ + e];
    }
    g_xef[idx] = v;
}

__global__ void init_state_kernel() {
    int i = blockIdx.x * blockDim.x + threadIdx.x;
    if (i < B_ * H_) {
        g_c[i] = 0.0f;
        g_hh[0][i] = __float2half(0.0f);
    }
    if (i < NBLK) g_flags[i] = 0u;
    if (i == 0) g_gen = 0u;
}

// ---------------------------------------------------------------------------
// PTX helpers
// ---------------------------------------------------------------------------
__device__ __forceinline__ void cp16(void* smem_dst, const void* gmem_src) {
    uint32_t s = (uint32_t)__cvta_generic_to_shared(smem_dst);
    asm volatile("cp.async.cg.shared.global [%0], [%1], 16;" :: "r"(s), "l"(gmem_src));
}

__device__ __forceinline__ void ldm_x4(uint32_t r[4], uint32_t addr) {
    asm volatile("ldmatrix.sync.aligned.m8n8.x4.shared.b16 {%0,%1,%2,%3}, [%4];"
                 : "=r"(r[0]), "=r"(r[1]), "=r"(r[2]), "=r"(r[3]) : "r"(addr));
}

__device__ __forceinline__ void mma_f16(
    float c[4], const uint32_t a[4], uint32_t b0, uint32_t b1)
{
    asm volatile(
        "mma.sync.aligned.m16n8k16.row.col.f32.f16.f16.f32 "
        "{%0,%1,%2,%3}, {%4,%5,%6,%7}, {%8,%9}, {%0,%1,%2,%3};"
        : "+f"(c[0]), "+f"(c[1]), "+f"(c[2]), "+f"(c[3])
        : "r"(a[0]), "r"(a[1]), "r"(a[2]), "r"(a[3]), "r"(b0), "r"(b1));
}

// ---------------------------------------------------------------------------
// smem layout (dynamic):
//   W tile    : 64 n-rows x pitch 520 fp16  (pitch 1040B: conflict-free ldm)
//   A stages  : 3 x [128 rows x 40] fp16    (k-chunk 32)
//   z         : 128 x 68 f32
//   xe        : 128 x 16 f32
//   xw        : 4 x 10 x 16 f32, bias: 64 f32
// ---------------------------------------------------------------------------
#define WPITCH 520
#define W_BYTES (64 * WPITCH * 2)            // 66560
#define APAD 40
#define A_ST_BYTES (128 * APAD * 2)          // 10240
#define A_OFF2 W_BYTES
#define Z_OFF (A_OFF2 + 3 * A_ST_BYTES)      // 97280
#define ZP 68
#define XE_OFF (Z_OFF + 128 * ZP * 4)        // 132096
#define XW_OFF (XE_OFF + 128 * 16 * 4)       // 140288
#define BI_OFF (XW_OFF + NGATE * E_ * 16 * 4)// 142848
#define SMEM_T (BI_OFF + 64 * 4)             // 143104

__global__ void __launch_bounds__(NT) lstm_persistent(
    const float* __restrict__ Wgx, const float* __restrict__ Wix,
    const float* __restrict__ Wfx, const float* __restrict__ Wox,
    const float* __restrict__ bg, const float* __restrict__ bi,
    const float* __restrict__ bf_, const float* __restrict__ bo)
{
    extern __shared__ __align__(16) char sm[];
    const int tid = threadIdx.x;
    const int bid = blockIdx.x;
    const int nt = bid & 31;
    const int mt = bid >> 5;
    const int bn = nt * 64;      // global col base (n = 4j+g)
    const int bj = nt * 16;      // j base
    const int bb = mt * 128;     // batch base
    const int w = tid >> 5;
    const int lane = tid & 31;
    const int gid = lane >> 2;
    const int tig = lane & 3;
    const int wm = (w >> 2) * 32;    // 4 m-groups of 32
    const int wn = (w & 3) * 16;     // 4 n-groups of 16

    const uint32_t SBase = (uint32_t)__cvta_generic_to_shared(sm);
    float* const z_s    = (float*)(sm + Z_OFF);
    float* const xe_s   = (float*)(sm + XE_OFF);
    float* const xw_s   = (float*)(sm + XW_OFF);
    float* const bias_s = (float*)(sm + BI_OFF);

    // ldmatrix per-lane offsets
    const uint32_t w_frag = SBase +
        ((wn + ((lane >> 4) & 1) * 8 + (lane & 7)) * WPITCH + ((lane >> 3) & 1) * 8) * 2;
    const uint32_t a_rel =
        ((wm + ((lane >> 3) & 1) * 8 + (lane & 7)) * APAD + ((lane >> 4) & 1) * 8) * 2;

    // ---- one-time prologue: W tile -> smem, xw/bias -> smem ----
    #pragma unroll
    for (int i = 0; i < 8; i++) {                    // 4096 segs of 16B
        int seg = tid + i * NT;
        int row = seg >> 6, ko = seg & 63;
        cp16(sm + row * (WPITCH * 2) + ko * 16, &g_Wt[(bn + row) * H_ + ko * 8]);
    }
    asm volatile("cp.async.commit_group;");
    {
        const float* const Wx[4] = {Wgx, Wix, Wfx, Wox};
        for (int i = tid; i < NGATE * E_ * 16; i += NT) {
            int g = i / (E_ * 16), rem = i % (E_ * 16);
            int e = rem / 16, jl = rem % 16;
            xw_s[i] = Wx[g][e * H_ + bj + jl];
        }
        const float* const bptr[4] = {bg, bi, bf_, bo};
        if (tid < 64) bias_s[tid] = bptr[tid >> 4][bj + (tid & 15)];
    }
    asm volatile("cp.async.wait_group 0;" ::: "memory");
    __syncthreads();

    // ---- time loop ----
    #pragma unroll 1
    for (int t = 0; t < T_; t++) {
        const int src = t & 1;
        const __half* __restrict__ hh = g_hh[src];
        __half* __restrict__ hh_out = g_hh[src ^ 1];

        auto load_chunk = [&](int stage, int k0) {
            char* sb = sm + A_OFF2 + stage * A_ST_BYTES;
            int r = tid >> 2, s8 = (tid & 3) * 8;    // 512 segs, 1/thread
            cp16(sb + (r * APAD + s8) * 2, &hh[(bb + r) * H_ + k0 + s8]);
            asm volatile("cp.async.commit_group;");
        };

        // xe for this step (rides in chunk 0's group)
        {
            int r = tid >> 2, q = (tid & 3) * 4;
            cp16(sm + XE_OFF + (r * 16 + q) * 4,
                 &g_xef[(t * B_ + bb + r) * 16 + q]);
        }
        load_chunk(0, 0);
        load_chunk(1, 32);

        float acc[4][4];
        #pragma unroll
        for (int i = 0; i < 4; i++)
            #pragma unroll
            for (int v = 0; v < 4; v++) acc[i][v] = 0.0f;

        #pragma unroll 1
        for (int kt = 0; kt < 16; kt++) {
            if (kt < 14) asm volatile("cp.async.wait_group 1;" ::: "memory");
            else         asm volatile("cp.async.wait_group 0;" ::: "memory");
            __syncthreads();
            if (kt + 2 < 16) load_chunk((kt + 2) % 3, (kt + 2) * 32);

            const uint32_t sb = SBase + A_OFF2 + (kt % 3) * A_ST_BYTES;
            uint32_t A0[2][4], A1[2][4], Bv[2][4];
            #pragma unroll
            for (int kk2 = 0; kk2 < 2; kk2++) {
                ldm_x4(A0[kk2], sb + a_rel + kk2 * 32);
                ldm_x4(A1[kk2], sb + a_rel + 16 * APAD * 2 + kk2 * 32);
                ldm_x4(Bv[kk2], w_frag + (kt * 32 + kk2 * 16) * 2);
            }
            #pragma unroll
            for (int kk2 = 0; kk2 < 2; kk2++) {
                mma_f16(acc[0], A0[kk2], Bv[kk2][0], Bv[kk2][1]);
                mma_f16(acc[1], A0[kk2], Bv[kk2][2], Bv[kk2][3]);
                mma_f16(acc[2], A1[kk2], Bv[kk2][0], Bv[kk2][1]);
                mma_f16(acc[3], A1[kk2], Bv[kk2][2], Bv[kk2][3]);
            }
        }

        // spill accs to z_s
        #pragma unroll
        for (int m2 = 0; m2 < 2; m2++) {
            const int row_l = wm + m2 * 16 + gid;
            #pragma unroll
            for (int nf = 0; nf < 2; nf++) {
                const int col = wn + nf * 8 + 2 * tig;
                const float* a = acc[m2 * 2 + nf];
                *(float2*)&z_s[row_l * ZP + col]       = make_float2(a[0], a[1]);
                *(float2*)&z_s[(row_l + 8) * ZP + col] = make_float2(a[2], a[3]);
            }
        }
        __syncthreads();

        // pointwise: 128 rows x 16 j = 2048 units / 512 threads = 4 reps
        #pragma unroll
        for (int rep = 0; rep < 4; rep++) {
            const int elem = tid + rep * NT;
            const int r = elem >> 4, jl = elem & 15;
            const int gr = bb + r, gj = bj + jl;

            float4 zv = *(const float4*)&z_s[r * ZP + 4 * jl];
            float zg = zv.x + bias_s[jl];
            float zi = zv.y + bias_s[16 + jl];
            float zf = zv.z + bias_s[32 + jl];
            float zo = zv.w + bias_s[48 + jl];

            #pragma unroll
            for (int e = 0; e < E_; e++) {
                float xv = xe_s[r * 16 + e];
                zg += xv * xw_s[(0 * E_ + e) * 16 + jl];
                zi += xv * xw_s[(1 * E_ + e) * 16 + jl];
                zf += xv * xw_s[(2 * E_ + e) * 16 + jl];
                zo += xv * xw_s[(3 * E_ + e) * 16 + jl];
            }

            float gg = tanhf(zg);
            float ii = 1.0f / (1.0f + __expf(-zi));
            float ff = 1.0f / (1.0f + __expf(-zf));
            float oo = 1.0f / (1.0f + __expf(-zo));

            float cn = gg * ii + g_c[gr * H_ + gj] * ff;
            float hn = tanhf(cn) * oo;
            g_c[gr * H_ + gj] = cn;
            hh_out[gr * H_ + gj] = __float2half(hn);
        }

        // ---- grid barrier: flags + generation ----
        __syncthreads();
        if (tid == 0) {
            __threadfence();
            g_flags[bid] = (unsigned)(t + 1);
        }
        if (bid == 0) {
            if (tid < NBLK) {
                while (g_flags[tid] < (unsigned)(t + 1)) { }
            }
            __syncthreads();
            if (tid == 0) {
                __threadfence();
                g_gen = (unsigned)(t + 1);
            }
        }
        if (tid == 0) {
            while (g_gen < (unsigned)(t + 1)) { }
        }
        __syncthreads();
    }
}

// ---------------------------------------------------------------------------
// Final projection: h from fp16 buffer 0 (after t=255).
// ---------------------------------------------------------------------------
__global__ void proj_kernel(const float* __restrict__ Wph,
                            const float* __restrict__ bp, float* __restrict__ out) {
    int i = blockIdx.x * blockDim.x + threadIdx.x;
    if (i >= B_ * C_) return;
    int b = i / C_;
    int c = i % C_;
    float acc = bp[c];
    #pragma unroll 8
    for (int k = 0; k < H_; k++) {
        acc += __half2float(g_hh[0][b * H_ + k]) * Wph[k * C_ + c];
    }
    out[i] = acc;
}

// ---------------------------------------------------------------------------
// Launch sequence (graph-capturable, single stream)
// ---------------------------------------------------------------------------
extern "C" void kernel_launch(void* const* d_in, const int* in_sizes, int n_in,
                              void* d_out, int out_size) {
    const int* x        = (const int*)d_in[0];       // int32 (JAX downcasts int64)
    const float* emb    = (const float*)d_in[1];
    const float* Wgx    = (const float*)d_in[2];
    const float* Wgh    = (const float*)d_in[3];
    const float* bg     = (const float*)d_in[4];
    const float* Wix    = (const float*)d_in[5];
    const float* Wih    = (const float*)d_in[6];
    const float* bi     = (const float*)d_in[7];
    const float* Wfx    = (const float*)d_in[8];
    const float* Wfh    = (const float*)d_in[9];
    const float* bf_    = (const float*)d_in[10];
    const float* Wox    = (const float*)d_in[11];
    const float* Woh    = (const float*)d_in[12];
    const float* bo     = (const float*)d_in[13];
    const float* Wph    = (const float*)d_in[14];
    const float* bp     = (const float*)d_in[15];
    float* out          = (float*)d_out;

    static bool attr_set = false;
    if (!attr_set) {
        cudaFuncSetAttribute(lstm_persistent,
                             cudaFuncAttributeMaxDynamicSharedMemorySize,
                             SMEM_T);
        attr_set = true;
    }

    prep_weights_kernel<<<(N_TOT * H_) / 256, 256>>>(Wgh, Wih, Wfh, Woh);
    prep_xe_kernel<<<(T_ * B_ * 16) / 256, 256>>>(x, emb);
    init_state_kernel<<<(B_ * H_ + 255) / 256, 256>>>();

    lstm_persistent<<<NBLK, NT, SMEM_T>>>(
        Wgx, Wix, Wfx, Wox, bg, bi, bf_, bo);

    proj_kernel<<<(B_ * C_ + 255) / 256, 256>>>(Wph, bp, out);
}